// round 3
// baseline (speedup 1.0000x reference)
#include <cuda_runtime.h>

#define T_STEPS 16384
#define X_DIM   512
#define H_DIM   1024
#define NBLK    128
#define ROWS_PER_BLK (H_DIM / NBLK)    // 8 rows per block
#define NTHREADS (ROWS_PER_BLK * 32)   // 256 threads, 1 warp per row
#define MBOX_PER_LANE (NBLK / 32)      // 4 mailbox copies per lane

// Private mailboxes: mbox[parity][block][row] = (tag<<32)|fp32, tag = t+1.
// Each consumer block polls ONLY its own contiguous 8KB slab -> no L2 line
// is ever polled by more than one SM. Producers push 128 copies (4 per lane).
// Double buffer by step parity: a producer reaches step t+2 (next write to
// the same buffer) only after gathering tag t+2, which requires every block
// to have published t+2, which requires them to have consumed t+1. Stale
// cross-replay tags can only match the same step index -> identical value.
__device__ unsigned long long g_mbox[2][NBLK][H_DIM];

__device__ __forceinline__ unsigned long long ld_relaxed_u64(const unsigned long long* p) {
    unsigned long long v;
    asm volatile("ld.relaxed.gpu.global.u64 %0, [%1];" : "=l"(v) : "l"(p) : "memory");
    return v;
}
__device__ __forceinline__ void st_relaxed_u64(unsigned long long* p, unsigned long long v) {
    asm volatile("st.relaxed.gpu.global.u64 [%0], %1;" :: "l"(p), "l"(v) : "memory");
}

__global__ void __launch_bounds__(NTHREADS, 1)
rnn_scan_kernel(const float* __restrict__ x_seq,
                const float* __restrict__ h0,
                const float* __restrict__ A_raw,
                const float* __restrict__ B,
                const float* __restrict__ c,
                float* __restrict__ out)
{
    const int warp = threadIdx.x >> 5;
    const int lane = threadIdx.x & 31;
    const int row  = blockIdx.x * ROWS_PER_BLK + warp;

    __shared__ float Bs[ROWS_PER_BLK][X_DIM];      // 16 KB
    __shared__ float h_sm[2][H_DIM];               // 8 KB double buffer

    // ---- Prologue: A = 0.9 I + 0.1 A_raw, row in registers.
    float a[32];
#pragma unroll
    for (int k = 0; k < 32; ++k) {
        int j = lane + 32 * k;
        float v = 0.1f * A_raw[(size_t)row * H_DIM + j];
        if (j == row) v += 0.9f;
        a[k] = v;
    }
    for (int i = threadIdx.x; i < ROWS_PER_BLK * X_DIM; i += NTHREADS) {
        int rr = i / X_DIM, jj = i % X_DIM;
        Bs[rr][jj] = B[((size_t)blockIdx.x * ROWS_PER_BLK + rr) * X_DIM + jj];
    }
    const float c_r = (lane == 0) ? c[row] : 0.0f;

    for (int i = threadIdx.x; i < H_DIM; i += NTHREADS)
        h_sm[0][i] = h0[i];
    __syncthreads();

    for (int t = 0; t < T_STEPS; ++t) {
        const int cur = t & 1;

        // ---- 1) Input projection partial (mostly L2 hits, overlaps FMA).
        const float* xt = x_seq + (size_t)t * X_DIM;
        float xv[X_DIM / 32];
#pragma unroll
        for (int k = 0; k < X_DIM / 32; ++k) xv[k] = xt[lane + 32 * k];
        float b0 = 0.f, b1 = 0.f, b2 = 0.f, b3 = 0.f;
#pragma unroll
        for (int k = 0; k < X_DIM / 32; k += 4) {
            b0 += Bs[warp][lane + 32 * (k + 0)] * xv[k + 0];
            b1 += Bs[warp][lane + 32 * (k + 1)] * xv[k + 1];
            b2 += Bs[warp][lane + 32 * (k + 2)] * xv[k + 2];
            b3 += Bs[warp][lane + 32 * (k + 3)] * xv[k + 3];
        }
        float acc = ((b0 + b1) + (b2 + b3)) + c_r;

        // ---- 2) A . h_t from smem (bank == lane, conflict-free).
        float hv[32];
#pragma unroll
        for (int k = 0; k < 32; ++k) hv[k] = h_sm[cur][lane + 32 * k];
        float s0 = 0.f, s1 = 0.f, s2 = 0.f, s3 = 0.f;
#pragma unroll
        for (int k = 0; k < 32; k += 4) {
            s0 += a[k + 0] * hv[k + 0];
            s1 += a[k + 1] * hv[k + 1];
            s2 += a[k + 2] * hv[k + 2];
            s3 += a[k + 3] * hv[k + 3];
        }
        acc += (s0 + s1) + (s2 + s3);

        // ---- 3) Reduce; every lane ends with the row sum.
#pragma unroll
        for (int off = 16; off; off >>= 1)
            acc += __shfl_xor_sync(0xffffffffu, acc, off);

        float hval = tanhf(acc);
        if (lane == 0)
            out[(size_t)t * H_DIM + row] = hval;

        // ---- 4) Push: each lane delivers this row to 4 private mailboxes.
        {
            unsigned long long w =
                ((unsigned long long)(unsigned)(t + 1) << 32) | __float_as_uint(hval);
            unsigned long long* base = &g_mbox[cur][0][0];
#pragma unroll
            for (int i = 0; i < MBOX_PER_LANE; ++i) {
                int m = lane * MBOX_PER_LANE + i;
                st_relaxed_u64(base + (size_t)m * H_DIM + row, w);
            }
        }

        // ---- 5) Gather h_{t+1} from OUR private mailbox (coalesced,
        // contention-free: no other SM ever touches these lines).
        if (t + 1 < T_STEPS) {
            const unsigned want = (unsigned)(t + 1);
            unsigned long long* slot = &g_mbox[cur][blockIdx.x][0];
            unsigned long long q[4];
#pragma unroll
            for (int k = 0; k < 4; ++k)
                q[k] = ld_relaxed_u64(&slot[threadIdx.x + NTHREADS * k]);
            for (;;) {
                bool miss = false;
#pragma unroll
                for (int k = 0; k < 4; ++k) {
                    if ((unsigned)(q[k] >> 32) != want) {
                        q[k] = ld_relaxed_u64(&slot[threadIdx.x + NTHREADS * k]);
                        if ((unsigned)(q[k] >> 32) != want) miss = true;
                    }
                }
                if (!miss) break;
            }
#pragma unroll
            for (int k = 0; k < 4; ++k)
                h_sm[cur ^ 1][threadIdx.x + NTHREADS * k] = __uint_as_float((unsigned)q[k]);
        }
        __syncthreads();
    }
}

extern "C" void kernel_launch(void* const* d_in, const int* in_sizes, int n_in,
                              void* d_out, int out_size)
{
    const float* x_seq = (const float*)d_in[0];
    const float* h0    = (const float*)d_in[1];
    const float* A_raw = (const float*)d_in[2];
    const float* B     = (const float*)d_in[3];
    const float* c     = (const float*)d_in[4];
    float* out = (float*)d_out;

    rnn_scan_kernel<<<NBLK, NTHREADS>>>(x_seq, h0, A_raw, B, c, out);
}

// round 4
// speedup vs baseline: 2.8678x; 2.8678x over previous
#include <cuda_runtime.h>

#define T_STEPS 16384
#define X_DIM   512
#define H_DIM   1024
#define NBLK    128
#define ROWS_PER_BLK 8                 // rows per block, 1 warp per row
#define NTHREADS 256
#define SHARDS  8                      // mailbox copies; 16 blocks poll each shard

// Tagged mailbox shards: word = (tag<<32)|fp32, tag = t+1 (0 == empty).
// Double-buffered by step parity; reuse is gated by the full-gather-before-
// next-push dependency. Cross-replay stale tags can only match the same step
// index -> identical (deterministic) value, so no reset is needed.
__device__ unsigned long long g_mbox[2][SHARDS][H_DIM];

__device__ __forceinline__ unsigned long long ld_relaxed_u64(const unsigned long long* p) {
    unsigned long long v;
    asm volatile("ld.relaxed.gpu.global.u64 %0, [%1];" : "=l"(v) : "l"(p) : "memory");
    return v;
}
__device__ __forceinline__ void st_relaxed_u64(unsigned long long* p, unsigned long long v) {
    asm volatile("st.relaxed.gpu.global.u64 [%0], %1;" :: "l"(p), "l"(v) : "memory");
}
__device__ __forceinline__ void prefetch_l2(const void* p) {
    asm volatile("prefetch.global.L2 [%0];" :: "l"(p));
}
__device__ __forceinline__ float fast_tanh(float x) {
    float xc = fminf(fmaxf(x, -10.0f), 10.0f);
    float e  = __expf(2.0f * xc);
    return __fdividef(e - 1.0f, e + 1.0f);
}

__global__ void __launch_bounds__(NTHREADS, 1)
rnn_scan_kernel(const float* __restrict__ x_seq,
                const float* __restrict__ h0,
                const float* __restrict__ A_raw,
                const float* __restrict__ B,
                const float* __restrict__ c,
                float* __restrict__ out)
{
    const int warp = threadIdx.x >> 5;
    const int lane = threadIdx.x & 31;
    const int row  = blockIdx.x * ROWS_PER_BLK + warp;

    __shared__ float4 Bs4[ROWS_PER_BLK][X_DIM / 4];   // 16 KB
    __shared__ float  h_sm[2][H_DIM];                 // 8 KB double buffer

    // ---- Prologue: A = 0.9 I + 0.1 A_raw, row in float4 registers.
    // a4[k] covers columns j = 4*lane + 128*k + {0..3}.
    const float4* Ar = (const float4*)(A_raw + (size_t)row * H_DIM);
    float4 a4[8];
#pragma unroll
    for (int k = 0; k < 8; ++k) {
        float4 v = Ar[lane + 32 * k];
        int j = 4 * (lane + 32 * k);
        v.x *= 0.1f; v.y *= 0.1f; v.z *= 0.1f; v.w *= 0.1f;
        if (j + 0 == row) v.x += 0.9f;
        if (j + 1 == row) v.y += 0.9f;
        if (j + 2 == row) v.z += 0.9f;
        if (j + 3 == row) v.w += 0.9f;
        a4[k] = v;
    }
    {
        const float4* Bg = (const float4*)(B + (size_t)blockIdx.x * ROWS_PER_BLK * X_DIM);
        for (int i = threadIdx.x; i < ROWS_PER_BLK * (X_DIM / 4); i += NTHREADS)
            Bs4[i / (X_DIM / 4)][i % (X_DIM / 4)] = Bg[i];
    }
    const float c_r = (lane == 0) ? c[row] : 0.0f;

    for (int i = threadIdx.x; i < H_DIM; i += NTHREADS)
        h_sm[0][i] = h0[i];

    // x for step 0 into registers.
    float4 xn[4];
    {
        const float4* xt = (const float4*)x_seq;
#pragma unroll
        for (int k = 0; k < 4; ++k) xn[k] = xt[lane + 32 * k];
        if (threadIdx.x < 16) prefetch_l2(x_seq + X_DIM + threadIdx.x * 32);
    }
    __syncthreads();

    // bx partial for step 0.
    float bxp;
    {
        float s0 = 0.f, s1 = 0.f;
#pragma unroll
        for (int k = 0; k < 4; ++k) {
            float4 b = Bs4[warp][lane + 32 * k];
            s0 += b.x * xn[k].x + b.z * xn[k].z;
            s1 += b.y * xn[k].y + b.w * xn[k].w;
        }
        bxp = s0 + s1;
    }

    const int shard = blockIdx.x >> 4;   // 16 blocks per shard

    for (int t = 0; t < T_STEPS; ++t) {
        const int cur = t & 1;

        // ---- 1) A . h_t (float4 smem loads, conflict-free) + bx partial.
        const float4* hp = (const float4*)h_sm[cur];
        float4 h4[8];
#pragma unroll
        for (int k = 0; k < 8; ++k) h4[k] = hp[lane + 32 * k];
        float s0 = bxp + c_r, s1 = 0.f, s2 = 0.f, s3 = 0.f;
#pragma unroll
        for (int k = 0; k < 8; ++k) {
            s0 += a4[k].x * h4[k].x;
            s1 += a4[k].y * h4[k].y;
            s2 += a4[k].z * h4[k].z;
            s3 += a4[k].w * h4[k].w;
        }
        float acc = (s0 + s1) + (s2 + s3);

        // ---- 2) Reduce; all lanes end with the row sum.
#pragma unroll
        for (int off = 16; off; off >>= 1)
            acc += __shfl_xor_sync(0xffffffffu, acc, off);

        float hval = fast_tanh(acc);
        if (lane == 0)
            out[(size_t)t * H_DIM + row] = hval;

        // ---- 3) Push to 8 shards (one STG.64, 8 active lanes -> 8 lines).
        {
            unsigned long long w =
                ((unsigned long long)(unsigned)(t + 1) << 32) | __float_as_uint(hval);
            if (lane < SHARDS)
                st_relaxed_u64(&g_mbox[cur][lane][row], w);
        }

        if (t + 1 < T_STEPS) {
            // ---- 4) Kick off x_{t+1} loads NOW; latency hides in the poll.
            const float4* xt1 = (const float4*)(x_seq + (size_t)(t + 1) * X_DIM);
#pragma unroll
            for (int k = 0; k < 4; ++k) xn[k] = xt1[lane + 32 * k];
            if (t + 2 < T_STEPS && threadIdx.x < 16)
                prefetch_l2(x_seq + (size_t)(t + 2) * X_DIM + threadIdx.x * 32);

            // ---- 5) Poll our shard (coalesced, 16 pollers/line max).
            const unsigned want = (unsigned)(t + 1);
            unsigned long long* slot = &g_mbox[cur][shard][0];
            unsigned long long q[4];
#pragma unroll
            for (int k = 0; k < 4; ++k)
                q[k] = ld_relaxed_u64(&slot[threadIdx.x + NTHREADS * k]);
            for (;;) {
                bool miss = false;
#pragma unroll
                for (int k = 0; k < 4; ++k) {
                    if ((unsigned)(q[k] >> 32) != want) {
                        q[k] = ld_relaxed_u64(&slot[threadIdx.x + NTHREADS * k]);
                        if ((unsigned)(q[k] >> 32) != want) miss = true;
                    }
                }
                if (!miss) break;
            }
#pragma unroll
            for (int k = 0; k < 4; ++k)
                h_sm[cur ^ 1][threadIdx.x + NTHREADS * k] = __uint_as_float((unsigned)q[k]);
            __syncthreads();

            // ---- 6) bx partial for t+1 (xn has landed by now).
            float b0 = 0.f, b1 = 0.f;
#pragma unroll
            for (int k = 0; k < 4; ++k) {
                float4 b = Bs4[warp][lane + 32 * k];
                b0 += b.x * xn[k].x + b.z * xn[k].z;
                b1 += b.y * xn[k].y + b.w * xn[k].w;
            }
            bxp = b0 + b1;
        }
    }
}

extern "C" void kernel_launch(void* const* d_in, const int* in_sizes, int n_in,
                              void* d_out, int out_size)
{
    const float* x_seq = (const float*)d_in[0];
    const float* h0    = (const float*)d_in[1];
    const float* A_raw = (const float*)d_in[2];
    const float* B     = (const float*)d_in[3];
    const float* c     = (const float*)d_in[4];
    float* out = (float*)d_out;

    rnn_scan_kernel<<<NBLK, NTHREADS>>>(x_seq, h0, A_raw, B, c, out);
}

// round 6
// speedup vs baseline: 3.1548x; 1.1001x over previous
#include <cuda_runtime.h>

#define T_STEPS 16384
#define X_DIM   512
#define H_DIM   1024
#define NBLK    128
#define ROWS_PER_BLK 8                 // rows per block, 1 warp per row
#define NTHREADS 256
#define SHARDS  8                      // mailbox copies; 16 blocks poll each shard

// Tagged mailbox shards: word = (tag<<32)|fp32, tag = t+1 (0 == empty).
// Double-buffered by step parity; buffer reuse is gated by the gather-before-
// next-push dependency. Cross-replay stale tags can only match the same step
// index -> identical (deterministic) value, so no reset is needed.
__device__ unsigned long long g_mbox[2][SHARDS][H_DIM];

__device__ __forceinline__ unsigned long long ld_relaxed_u64(const unsigned long long* p) {
    unsigned long long v;
    asm volatile("ld.relaxed.gpu.global.u64 %0, [%1];" : "=l"(v) : "l"(p) : "memory");
    return v;
}
__device__ __forceinline__ void st_relaxed_u64(unsigned long long* p, unsigned long long v) {
    asm volatile("st.relaxed.gpu.global.u64 [%0], %1;" :: "l"(p), "l"(v) : "memory");
}
__device__ __forceinline__ void prefetch_l2(const void* p) {
    asm volatile("prefetch.global.L2 [%0];" :: "l"(p));
}
// MUFU.TANH — single ~16cyc op. Per-step err ~5e-4; the recurrence is
// contracting (R4 evidence: fast_tanh err did not accumulate), so final
// rel_err stays bounded. Watch the bench rel_err.
__device__ __forceinline__ float tanh_fast(float x) {
    float y;
    asm volatile("tanh.approx.f32 %0, %1;" : "=f"(y) : "f"(x));
    return y;
}

__global__ void __launch_bounds__(NTHREADS, 1)
rnn_scan_kernel(const float* __restrict__ x_seq,
                const float* __restrict__ h0,
                const float* __restrict__ A_raw,
                const float* __restrict__ B,
                const float* __restrict__ c,
                float* __restrict__ out)
{
    const int warp = threadIdx.x >> 5;
    const int lane = threadIdx.x & 31;
    const int row  = blockIdx.x * ROWS_PER_BLK + warp;

    __shared__ float4 Bs4[ROWS_PER_BLK][X_DIM / 4];   // 16 KB
    __shared__ float  h_sm[2][H_DIM];                 // 8 KB double buffer

    // ---- Prologue: A = 0.9 I + 0.1 A_raw, row in float4 registers.
    const float4* Ar = (const float4*)(A_raw + (size_t)row * H_DIM);
    float4 a4[8];
#pragma unroll
    for (int k = 0; k < 8; ++k) {
        float4 v = Ar[lane + 32 * k];
        int j = 4 * (lane + 32 * k);
        v.x *= 0.1f; v.y *= 0.1f; v.z *= 0.1f; v.w *= 0.1f;
        if (j + 0 == row) v.x += 0.9f;
        if (j + 1 == row) v.y += 0.9f;
        if (j + 2 == row) v.z += 0.9f;
        if (j + 3 == row) v.w += 0.9f;
        a4[k] = v;
    }
    {
        const float4* Bg = (const float4*)(B + (size_t)blockIdx.x * ROWS_PER_BLK * X_DIM);
        for (int i = threadIdx.x; i < ROWS_PER_BLK * (X_DIM / 4); i += NTHREADS)
            Bs4[i / (X_DIM / 4)][i % (X_DIM / 4)] = Bg[i];
    }
    const float c_r = (lane == 0) ? c[row] : 0.0f;

    for (int i = threadIdx.x; i < H_DIM; i += NTHREADS)
        h_sm[0][i] = h0[i];

    // x for step 0 into registers.
    float4 xn[4];
    {
        const float4* xt = (const float4*)x_seq;
#pragma unroll
        for (int k = 0; k < 4; ++k) xn[k] = xt[lane + 32 * k];
        if (threadIdx.x < 16) prefetch_l2(x_seq + X_DIM + threadIdx.x * 32);
    }
    __syncthreads();

    // bx partial for step 0.
    float bxp;
    {
        float s0 = 0.f, s1 = 0.f;
#pragma unroll
        for (int k = 0; k < 4; ++k) {
            float4 b = Bs4[warp][lane + 32 * k];
            s0 += b.x * xn[k].x + b.z * xn[k].z;
            s1 += b.y * xn[k].y + b.w * xn[k].w;
        }
        bxp = s0 + s1;
    }

    const int shard = blockIdx.x >> 4;   // 16 blocks per shard

    for (int t = 0; t < T_STEPS; ++t) {
        const int cur = t & 1;

        // ---- 1) A . h_t (float4 LDS, conflict-free) + bx partial.
        const float4* hp = (const float4*)h_sm[cur];
        float4 h4[8];
#pragma unroll
        for (int k = 0; k < 8; ++k) h4[k] = hp[lane + 32 * k];
        float s0 = bxp + c_r, s1 = 0.f, s2 = 0.f, s3 = 0.f;
#pragma unroll
        for (int k = 0; k < 8; ++k) {
            s0 += a4[k].x * h4[k].x;
            s1 += a4[k].y * h4[k].y;
            s2 += a4[k].z * h4[k].z;
            s3 += a4[k].w * h4[k].w;
        }
        float acc = (s0 + s1) + (s2 + s3);

        // ---- 2) Butterfly reduce (redux.f32 doesn't exist on sm_103).
#pragma unroll
        for (int off = 16; off; off >>= 1)
            acc += __shfl_xor_sync(0xffffffffu, acc, off);

        float hval = tanh_fast(acc);

        // ---- 3) Push FIRST (critical path); out-store on a non-push lane.
        {
            unsigned long long w =
                ((unsigned long long)(unsigned)(t + 1) << 32) | __float_as_uint(hval);
            if (lane < SHARDS)
                st_relaxed_u64(&g_mbox[cur][lane][row], w);
        }
        if (lane == 8)
            out[(size_t)t * H_DIM + row] = hval;

        if (t + 1 < T_STEPS) {
            // ---- 4) Issue x_{t+1} loads and mailbox probes back-to-back,
            // THEN compute bx: its xn stall overlaps the probes' L2 trip.
            const float4* xt1 = (const float4*)(x_seq + (size_t)(t + 1) * X_DIM);
#pragma unroll
            for (int k = 0; k < 4; ++k) xn[k] = xt1[lane + 32 * k];

            const unsigned want = (unsigned)(t + 1);
            unsigned long long* slot = &g_mbox[cur][shard][0];
            unsigned long long q[4];
#pragma unroll
            for (int k = 0; k < 4; ++k)
                q[k] = ld_relaxed_u64(&slot[threadIdx.x + NTHREADS * k]);

            if (t + 2 < T_STEPS && threadIdx.x < 16)
                prefetch_l2(x_seq + (size_t)(t + 2) * X_DIM + threadIdx.x * 32);

            float b0 = 0.f, b1 = 0.f;
#pragma unroll
            for (int k = 0; k < 4; ++k) {
                float4 b = Bs4[warp][lane + 32 * k];
                b0 += b.x * xn[k].x + b.z * xn[k].z;
                b1 += b.y * xn[k].y + b.w * xn[k].w;
            }
            bxp = b0 + b1;

            // ---- 5) Check probes (results landed during bx); retry misses.
            for (;;) {
                bool miss = false;
#pragma unroll
                for (int k = 0; k < 4; ++k) {
                    if ((unsigned)(q[k] >> 32) != want) {
                        q[k] = ld_relaxed_u64(&slot[threadIdx.x + NTHREADS * k]);
                        if ((unsigned)(q[k] >> 32) != want) miss = true;
                    }
                }
                if (!miss) break;
            }
#pragma unroll
            for (int k = 0; k < 4; ++k)
                h_sm[cur ^ 1][threadIdx.x + NTHREADS * k] = __uint_as_float((unsigned)q[k]);
            __syncthreads();
        }
    }
}

extern "C" void kernel_launch(void* const* d_in, const int* in_sizes, int n_in,
                              void* d_out, int out_size)
{
    const float* x_seq = (const float*)d_in[0];
    const float* h0    = (const float*)d_in[1];
    const float* A_raw = (const float*)d_in[2];
    const float* B     = (const float*)d_in[3];
    const float* c     = (const float*)d_in[4];
    float* out = (float*)d_out;

    rnn_scan_kernel<<<NBLK, NTHREADS>>>(x_seq, h0, A_raw, B, c, out);
}